// round 13
// baseline (speedup 1.0000x reference)
#include <cuda_runtime.h>
#include <math.h>

namespace {
constexpr int B  = 2;
constexpr int S  = 2048;
constexpr int D  = 512;
constexpr int H  = 8;
constexpr int DK = 64;
constexpr int NB = B * S;
constexpr int BH = B * H;
constexpr int DH = D / 2;
constexpr float DECAY = 0.02f;
constexpr float LN_EPS = 1e-5f;
}

// ---------------- device scratch ----------------
__device__ float g_q[BH * S * DK];      // (b,h,s,dk)
__device__ float g_k[BH * S * DK];
__device__ float g_v[BH * S * DK];
__device__ float g_o[NB * D];           // token-major (n, h*64+dk)
__device__ float g_proj[NB * D];
__device__ float g_hidden[NB * DH];
__device__ float g_gate[NB];
__device__ float g_rowsum[BH * S];
__device__ float g_decay[S];

// ---------------- tf32 helpers ----------------
__device__ __forceinline__ unsigned cvt_tf32(float f) {
    unsigned u;
    asm("cvt.rna.tf32.f32 %0, %1;" : "=r"(u) : "f"(f));
    return u;
}
__device__ __forceinline__ void split_tf32(float a, unsigned &hi, unsigned &lo) {
    hi = cvt_tf32(a);
    lo = cvt_tf32(a - __uint_as_float(hi));
}
__device__ __forceinline__ void mma8(float (&c)[4], const unsigned (&a)[4],
                                     const unsigned (&b)[2]) {
    asm volatile(
        "mma.sync.aligned.m16n8k8.row.col.f32.tf32.tf32.f32 "
        "{%0,%1,%2,%3}, {%4,%5,%6,%7}, {%8,%9}, {%0,%1,%2,%3};"
        : "+f"(c[0]), "+f"(c[1]), "+f"(c[2]), "+f"(c[3])
        : "r"(a[0]), "r"(a[1]), "r"(a[2]), "r"(a[3]), "r"(b[0]), "r"(b[1]));
}

// ---------------- init ----------------
__global__ void init_kernel() {
    int idx = blockIdx.x * blockDim.x + threadIdx.x;
    if (idx < BH * S) g_rowsum[idx] = 0.0f;
    if (idx < S)      g_decay[idx] = expf(-DECAY * (float)idx);
}

// ---------------- tf32 GEMM core v2: pre-split 2-pass, 128x128 tile, BK=16 ----------------
__device__ __forceinline__ void gemm_core(
    const float* __restrict__ A, const float* __restrict__ W, int N,
    int row0, int col0, float* Ahi, float* Alo, float* Bs, float (&acc)[2][8][4])
{
    const int tid = threadIdx.x, lane = tid & 31, wid = tid >> 5;
    const int g = lane >> 2, t4 = lane & 3, wm = wid >> 1, wn = wid & 1;
    const int ar = tid >> 1, ak = (tid & 1) * 8;
    const int bk = tid >> 4, bc = (tid & 15) * 4;

    const float* Ap = A + (size_t)(row0 + ar) * 512 + ak;
    const float* Wp = W + (size_t)bk * N + col0 + bc;

    float4 ra0 = *(const float4*)Ap, ra1 = *(const float4*)(Ap + 4);
    float4 rb0 = *(const float4*)Wp, rb1 = *(const float4*)(Wp + 64);

    for (int k0 = 0; k0 < 512; k0 += 16) {
        {
            unsigned h0, l0, h1, l1, h2, l2, h3, l3;
            split_tf32(ra0.x, h0, l0); split_tf32(ra0.y, h1, l1);
            split_tf32(ra0.z, h2, l2); split_tf32(ra0.w, h3, l3);
            *(float4*)&Ahi[ar * 20 + ak] = make_float4(
                __uint_as_float(h0), __uint_as_float(h1),
                __uint_as_float(h2), __uint_as_float(h3));
            *(float4*)&Alo[ar * 20 + ak] = make_float4(
                __uint_as_float(l0), __uint_as_float(l1),
                __uint_as_float(l2), __uint_as_float(l3));
            split_tf32(ra1.x, h0, l0); split_tf32(ra1.y, h1, l1);
            split_tf32(ra1.z, h2, l2); split_tf32(ra1.w, h3, l3);
            *(float4*)&Ahi[ar * 20 + ak + 4] = make_float4(
                __uint_as_float(h0), __uint_as_float(h1),
                __uint_as_float(h2), __uint_as_float(h3));
            *(float4*)&Alo[ar * 20 + ak + 4] = make_float4(
                __uint_as_float(l0), __uint_as_float(l1),
                __uint_as_float(l2), __uint_as_float(l3));
        }
        *(float4*)&Bs[bk * 132 + bc] = make_float4(
            __uint_as_float(cvt_tf32(rb0.x)), __uint_as_float(cvt_tf32(rb0.y)),
            __uint_as_float(cvt_tf32(rb0.z)), __uint_as_float(cvt_tf32(rb0.w)));
        *(float4*)&Bs[bk * 132 + bc + 64] = make_float4(
            __uint_as_float(cvt_tf32(rb1.x)), __uint_as_float(cvt_tf32(rb1.y)),
            __uint_as_float(cvt_tf32(rb1.z)), __uint_as_float(cvt_tf32(rb1.w)));
        __syncthreads();
        if (k0 + 16 < 512) {
            ra0 = *(const float4*)(Ap + k0 + 16);
            ra1 = *(const float4*)(Ap + k0 + 20);
            const float* w2 = Wp + (size_t)(k0 + 16) * N;
            rb0 = *(const float4*)w2;
            rb1 = *(const float4*)(w2 + 64);
        }
        #pragma unroll
        for (int ks = 0; ks < 2; ks++) {
            const int kk = ks * 8;
            unsigned ahi[2][4], alo[2][4], bb[8][2];
            #pragma unroll
            for (int mt = 0; mt < 2; mt++) {
                int base = (wm * 32 + mt * 16 + g) * 20 + kk;
                ahi[mt][0] = __float_as_uint(Ahi[base + t4]);
                ahi[mt][1] = __float_as_uint(Ahi[base + 8 * 20 + t4]);
                ahi[mt][2] = __float_as_uint(Ahi[base + t4 + 4]);
                ahi[mt][3] = __float_as_uint(Ahi[base + 8 * 20 + t4 + 4]);
                alo[mt][0] = __float_as_uint(Alo[base + t4]);
                alo[mt][1] = __float_as_uint(Alo[base + 8 * 20 + t4]);
                alo[mt][2] = __float_as_uint(Alo[base + t4 + 4]);
                alo[mt][3] = __float_as_uint(Alo[base + 8 * 20 + t4 + 4]);
            }
            #pragma unroll
            for (int nt = 0; nt < 8; nt++) {
                int n = wn * 64 + nt * 8 + g;
                bb[nt][0] = __float_as_uint(Bs[(kk + t4) * 132 + n]);
                bb[nt][1] = __float_as_uint(Bs[(kk + t4 + 4) * 132 + n]);
            }
            #pragma unroll
            for (int mt = 0; mt < 2; mt++)
                #pragma unroll
                for (int nt = 0; nt < 8; nt++)
                    mma8(acc[mt][nt], ahi[mt], bb[nt]);
            #pragma unroll
            for (int mt = 0; mt < 2; mt++)
                #pragma unroll
                for (int nt = 0; nt < 8; nt++)
                    mma8(acc[mt][nt], alo[mt], bb[nt]);
        }
        __syncthreads();
    }
}

// ---------------- QKV projection via mma ----------------
__global__ __launch_bounds__(256, 2) void qkv_mma_kernel(
    const float* __restrict__ x,
    const float* __restrict__ wq, const float* __restrict__ bq,
    const float* __restrict__ wk, const float* __restrict__ bk_,
    const float* __restrict__ wv, const float* __restrict__ bv)
{
    __shared__ __align__(16) float Ahi[128 * 20];
    __shared__ __align__(16) float Alo[128 * 20];
    __shared__ __align__(16) float Bs[16 * 132];

    const float* W; const float* bias; float* out;
    if (blockIdx.z == 0)      { W = wq; bias = bq;  out = g_q; }
    else if (blockIdx.z == 1) { W = wk; bias = bk_; out = g_k; }
    else                      { W = wv; bias = bv;  out = g_v; }

    const int row0 = blockIdx.y * 128, col0 = blockIdx.x * 128;
    float acc[2][8][4] = {};
    gemm_core(x, W, 512, row0, col0, Ahi, Alo, Bs, acc);

    const int tid = threadIdx.x, lane = tid & 31, wid = tid >> 5;
    const int g = lane >> 2, t4 = lane & 3, wm = wid >> 1, wn = wid & 1;

    #pragma unroll
    for (int mt = 0; mt < 2; mt++) {
        int n0 = row0 + wm * 32 + mt * 16 + g;
        int n1 = n0 + 8;
        int b0i = n0 >> 11, s0 = n0 & 2047;
        int b1i = n1 >> 11, s1 = n1 & 2047;
        #pragma unroll
        for (int nt = 0; nt < 8; nt++) {
            int c0 = col0 + wn * 64 + nt * 8 + 2 * t4;
            int h = c0 >> 6, dk = c0 & 63;
            float bb0 = bias[c0], bb1 = bias[c0 + 1];
            *(float2*)&out[(((size_t)(b0i * H + h)) * S + s0) * DK + dk] =
                make_float2(acc[mt][nt][0] + bb0, acc[mt][nt][1] + bb1);
            *(float2*)&out[(((size_t)(b1i * H + h)) * S + s1) * DK + dk] =
                make_float2(acc[mt][nt][2] + bb0, acc[mt][nt][3] + bb1);
        }
    }
}

// ---------------- generic projection via mma (1: oproj, 2: hidden+relu) ----------------
template<int MODE>
__global__ __launch_bounds__(256, 2) void proj_mma_kernel(
    const float* __restrict__ Ain, const float* __restrict__ W,
    const float* __restrict__ bias, int N)
{
    __shared__ __align__(16) float Ahi[128 * 20];
    __shared__ __align__(16) float Alo[128 * 20];
    __shared__ __align__(16) float Bs[16 * 132];

    const float* A = (MODE == 1) ? g_o : Ain;
    float* C = (MODE == 1) ? g_proj : g_hidden;

    const int row0 = blockIdx.y * 128, col0 = blockIdx.x * 128;
    float acc[2][8][4] = {};
    gemm_core(A, W, N, row0, col0, Ahi, Alo, Bs, acc);

    const int tid = threadIdx.x, lane = tid & 31, wid = tid >> 5;
    const int g = lane >> 2, t4 = lane & 3, wm = wid >> 1, wn = wid & 1;

    #pragma unroll
    for (int mt = 0; mt < 2; mt++) {
        int n0 = row0 + wm * 32 + mt * 16 + g;
        int n1 = n0 + 8;
        #pragma unroll
        for (int nt = 0; nt < 8; nt++) {
            int c0 = col0 + wn * 64 + nt * 8 + 2 * t4;
            float bb0 = bias[c0], bb1 = bias[c0 + 1];
            float v0 = acc[mt][nt][0] + bb0, v1 = acc[mt][nt][1] + bb1;
            float v2 = acc[mt][nt][2] + bb0, v3 = acc[mt][nt][3] + bb1;
            if (MODE == 2) {
                v0 = fmaxf(v0, 0.0f); v1 = fmaxf(v1, 0.0f);
                v2 = fmaxf(v2, 0.0f); v3 = fmaxf(v3, 0.0f);
            }
            *(float2*)&C[(size_t)n0 * N + c0] = make_float2(v0, v1);
            *(float2*)&C[(size_t)n1 * N + c0] = make_float2(v2, v3);
        }
    }
}

// ---------------- scores: 2-pass tf32 mma, pre-split smem, decay window ----------------
__global__ __launch_bounds__(256, 2) void scores_kernel(float* __restrict__ attn)
{
    extern __shared__ __align__(16) float sm[];
    float* Qhi = sm;
    float* Qlo = sm + 128 * 68;
    float* Kt  = sm + 2 * 128 * 68;
    float* ssum = sm + 3 * 128 * 68;
    float* dwin = ssum + 128;

    const int bh = blockIdx.z;
    const int row0 = blockIdx.y * 128;
    const int col0 = blockIdx.x * 128;
    const int tid = threadIdx.x, lane = tid & 31, wid = tid >> 5;
    const int g = lane >> 2, t4 = lane & 3, wm = wid >> 1, wn = wid & 1;

    const float* qb = g_q + ((size_t)bh * S + row0) * DK;
    const float* kb = g_k + ((size_t)bh * S + col0) * DK;

    #pragma unroll
    for (int i = 0; i < 8; i++) {
        int lin = i * 256 + tid;
        int r = lin >> 4, c4 = (lin & 15) * 4;
        float4 qv = *(const float4*)&qb[r * DK + c4];
        float4 kv = *(const float4*)&kb[r * DK + c4];
        unsigned h0, l0, h1, l1, h2, l2, h3, l3;
        split_tf32(qv.x, h0, l0); split_tf32(qv.y, h1, l1);
        split_tf32(qv.z, h2, l2); split_tf32(qv.w, h3, l3);
        *(float4*)&Qhi[r * 68 + c4] = make_float4(
            __uint_as_float(h0), __uint_as_float(h1),
            __uint_as_float(h2), __uint_as_float(h3));
        *(float4*)&Qlo[r * 68 + c4] = make_float4(
            __uint_as_float(l0), __uint_as_float(l1),
            __uint_as_float(l2), __uint_as_float(l3));
        *(float4*)&Kt[r * 68 + c4] = make_float4(
            __uint_as_float(cvt_tf32(kv.x)), __uint_as_float(cvt_tf32(kv.y)),
            __uint_as_float(cvt_tf32(kv.z)), __uint_as_float(cvt_tf32(kv.w)));
    }
    if (tid < 128) ssum[tid] = 0.0f;
    {
        int d = row0 - col0 - 127 + tid;
        dwin[tid] = (d >= 0 && d < S) ? g_decay[d] : 0.0f;
    }
    __syncthreads();

    float acc[2][8][4] = {};
    #pragma unroll
    for (int ks = 0; ks < 8; ks++) {
        const int kk = ks * 8;
        unsigned ahi[2][4], alo[2][4], bb[8][2];
        #pragma unroll
        for (int mt = 0; mt < 2; mt++) {
            int base = (wm * 32 + mt * 16 + g) * 68 + kk;
            ahi[mt][0] = __float_as_uint(Qhi[base + t4]);
            ahi[mt][1] = __float_as_uint(Qhi[base + 8 * 68 + t4]);
            ahi[mt][2] = __float_as_uint(Qhi[base + t4 + 4]);
            ahi[mt][3] = __float_as_uint(Qhi[base + 8 * 68 + t4 + 4]);
            alo[mt][0] = __float_as_uint(Qlo[base + t4]);
            alo[mt][1] = __float_as_uint(Qlo[base + 8 * 68 + t4]);
            alo[mt][2] = __float_as_uint(Qlo[base + t4 + 4]);
            alo[mt][3] = __float_as_uint(Qlo[base + 8 * 68 + t4 + 4]);
        }
        #pragma unroll
        for (int nt = 0; nt < 8; nt++) {
            int n = wn * 64 + nt * 8 + g;
            bb[nt][0] = __float_as_uint(Kt[n * 68 + kk + t4]);
            bb[nt][1] = __float_as_uint(Kt[n * 68 + kk + t4 + 4]);
        }
        #pragma unroll
        for (int mt = 0; mt < 2; mt++)
            #pragma unroll
            for (int nt = 0; nt < 8; nt++)
                mma8(acc[mt][nt], ahi[mt], bb[nt]);
        #pragma unroll
        for (int mt = 0; mt < 2; mt++)
            #pragma unroll
            for (int nt = 0; nt < 8; nt++)
                mma8(acc[mt][nt], alo[mt], bb[nt]);
    }

    float rsum[2][2] = {};
    #pragma unroll
    for (int mt = 0; mt < 2; mt++) {
        int rl = wm * 32 + mt * 16 + g;
        int gi0 = row0 + rl, gi1 = gi0 + 8;
        #pragma unroll
        for (int nt = 0; nt < 8; nt++) {
            int cl = wn * 64 + nt * 8 + 2 * t4;
            int gj = col0 + cl;
            int ib = rl - cl + 127;
            float v0 = acc[mt][nt][0] * 0.125f + dwin[ib];
            float v1 = acc[mt][nt][1] * 0.125f + dwin[ib - 1];
            float v2 = acc[mt][nt][2] * 0.125f + dwin[ib + 8];
            float v3 = acc[mt][nt][3] * 0.125f + dwin[ib + 7];
            float p0 = __expf(v0), p1 = __expf(v1);
            float p2 = __expf(v2), p3 = __expf(v3);
            rsum[mt][0] += p0 + p1;
            rsum[mt][1] += p2 + p3;
            *(float2*)&attn[((size_t)bh * S + gi0) * S + gj] = make_float2(p0, p1);
            *(float2*)&attn[((size_t)bh * S + gi1) * S + gj] = make_float2(p2, p3);
        }
    }
    #pragma unroll
    for (int mt = 0; mt < 2; mt++)
        #pragma unroll
        for (int h2 = 0; h2 < 2; h2++) {
            float v = rsum[mt][h2];
            v += __shfl_xor_sync(0xffffffffu, v, 1);
            v += __shfl_xor_sync(0xffffffffu, v, 2);
            if (t4 == 0) atomicAdd(&ssum[wm * 32 + mt * 16 + h2 * 8 + g], v);
        }
    __syncthreads();
    if (tid < 128) atomicAdd(&g_rowsum[(size_t)bh * S + row0 + tid], ssum[tid]);
}

// ---------------- attn@V v4: 128-row pipelined, single-tf32 P (1-pass) ----------------
// Block = 128q x 64(DK), 32 k-slabs of 64 with register prefetch.
// Smem floats: Phi[128*68] + Vt[64*72] = 13312 (53248 B).
__global__ __launch_bounds__(256, 2) void attnv_kernel(float* __restrict__ attn)
{
    extern __shared__ __align__(16) float sm[];
    float* Phi = sm;                  // [128][68]
    float* Vt  = sm + 128 * 68;       // [64][72]

    const int bh = blockIdx.y, row0 = blockIdx.x * 128;
    const int bb = bh >> 3, hh = bh & 7;
    const int tid = threadIdx.x, lane = tid & 31, wid = tid >> 5;
    const int g = lane >> 2, t4 = lane & 3, wm = wid >> 1, wn = wid & 1;

    const int r_p = tid >> 4;
    const int c4 = (tid & 15) * 4;

    float* gp0 = attn + ((size_t)bh * S + row0 + r_p) * S + c4;
    const float* vp0 = g_v + ((size_t)bh * S + r_p) * DK + c4;

    float invr[8];
    #pragma unroll
    for (int i = 0; i < 8; i++)
        invr[i] = 1.0f / g_rowsum[(size_t)bh * S + row0 + i * 16 + r_p];

    float acc[2][4][4] = {};

    // prologue: load slab 0
    float4 pv[8], vv[4];
    #pragma unroll
    for (int i = 0; i < 8; i++) pv[i] = *(const float4*)(gp0 + (size_t)i * 16 * S);
    #pragma unroll
    for (int i = 0; i < 4; i++) vv[i] = *(const float4*)(vp0 + i * 16 * DK);

    for (int kt = 0; kt < 32; kt++) {
        // ---- stage: scale, writeback attn, single tf32 cvt -> smem ----
        #pragma unroll
        for (int i = 0; i < 8; i++) {
            int r = i * 16 + r_p;
            float4 a = pv[i];
            float inv = invr[i];
            a.x *= inv; a.y *= inv; a.z *= inv; a.w *= inv;
            *(float4*)(gp0 + (size_t)i * 16 * S) = a;
            *(float4*)&Phi[r * 68 + c4] = make_float4(
                __uint_as_float(cvt_tf32(a.x)), __uint_as_float(cvt_tf32(a.y)),
                __uint_as_float(cvt_tf32(a.z)), __uint_as_float(cvt_tf32(a.w)));
        }
        #pragma unroll
        for (int i = 0; i < 4; i++) {
            int r = i * 16 + r_p;
            *(float4*)&Vt[r * 72 + c4] = make_float4(
                __uint_as_float(cvt_tf32(vv[i].x)), __uint_as_float(cvt_tf32(vv[i].y)),
                __uint_as_float(cvt_tf32(vv[i].z)), __uint_as_float(cvt_tf32(vv[i].w)));
        }
        gp0 += 64;
        __syncthreads();

        // ---- prefetch next slab (hidden under mma) ----
        if (kt + 1 < 32) {
            #pragma unroll
            for (int i = 0; i < 8; i++)
                pv[i] = *(const float4*)(gp0 + (size_t)i * 16 * S);
            const float* vp = vp0 + (size_t)(kt + 1) * 64 * DK;
            #pragma unroll
            for (int i = 0; i < 4; i++)
                vv[i] = *(const float4*)(vp + i * 16 * DK);
        }

        // ---- compute: single-pass mma ----
        #pragma unroll
        for (int ks = 0; ks < 8; ks++) {
            const int kk = ks * 8;
            unsigned ahi[2][4], bb2[4][2];
            #pragma unroll
            for (int mt = 0; mt < 2; mt++) {
                int base = (wm * 32 + mt * 16 + g) * 68 + kk;
                ahi[mt][0] = __float_as_uint(Phi[base + t4]);
                ahi[mt][1] = __float_as_uint(Phi[base + 8 * 68 + t4]);
                ahi[mt][2] = __float_as_uint(Phi[base + t4 + 4]);
                ahi[mt][3] = __float_as_uint(Phi[base + 8 * 68 + t4 + 4]);
            }
            #pragma unroll
            for (int nt = 0; nt < 4; nt++) {
                int n = wn * 32 + nt * 8 + g;
                bb2[nt][0] = __float_as_uint(Vt[(kk + t4) * 72 + n]);
                bb2[nt][1] = __float_as_uint(Vt[(kk + t4 + 4) * 72 + n]);
            }
            #pragma unroll
            for (int mt = 0; mt < 2; mt++)
                #pragma unroll
                for (int nt = 0; nt < 4; nt++)
                    mma8(acc[mt][nt], ahi[mt], bb2[nt]);
        }
        __syncthreads();
    }

    // O store, token-major
    #pragma unroll
    for (int mt = 0; mt < 2; mt++) {
        int rl = wm * 32 + mt * 16 + g;
        size_t tok0 = (size_t)bb * S + row0 + rl;
        size_t tok1 = tok0 + 8;
        #pragma unroll
        for (int nt = 0; nt < 4; nt++) {
            int dk = wn * 32 + nt * 8 + 2 * t4;
            *(float2*)&g_o[tok0 * D + hh * 64 + dk] =
                make_float2(acc[mt][nt][0], acc[mt][nt][1]);
            *(float2*)&g_o[tok1 * D + hh * 64 + dk] =
                make_float2(acc[mt][nt][2], acc[mt][nt][3]);
        }
    }
}

// ---------------- gate scalar ----------------
__global__ void gate_kernel(const float* __restrict__ g2w,
                            const float* __restrict__ g2b)
{
    int warp = (blockIdx.x * blockDim.x + threadIdx.x) >> 5;
    int lane = threadIdx.x & 31;
    if (warp >= NB) return;
    float sum = 0.0f;
    #pragma unroll
    for (int i = 0; i < DH / 32; i++)
        sum += g_hidden[warp * DH + i * 32 + lane] * g2w[i * 32 + lane];
    #pragma unroll
    for (int off = 16; off; off >>= 1)
        sum += __shfl_down_sync(0xffffffffu, sum, off);
    if (lane == 0)
        g_gate[warp] = 1.0f / (1.0f + expf(-(sum + g2b[0])));
}

// ---------------- gated residual + LayerNorm ----------------
__global__ __launch_bounds__(256) void ln_kernel(
    const float* __restrict__ x,
    const float* __restrict__ lng, const float* __restrict__ lnb,
    float* __restrict__ y)
{
    __shared__ float s1[8], s2[8];
    const int n = blockIdx.x;
    const int tid = threadIdx.x;
    const float g = g_gate[n];

    int j0 = tid * 2;
    float2 pr = *(const float2*)&g_proj[n * D + j0];
    float2 xr = *(const float2*)&x[n * D + j0];
    float o0 = pr.x * g + xr.x * (1.0f - g);
    float o1 = pr.y * g + xr.y * (1.0f - g);

    float sum = o0 + o1, sq = o0 * o0 + o1 * o1;
    #pragma unroll
    for (int off = 16; off; off >>= 1) {
        sum += __shfl_down_sync(0xffffffffu, sum, off);
        sq  += __shfl_down_sync(0xffffffffu, sq,  off);
    }
    int wid = tid >> 5, lane = tid & 31;
    if (lane == 0) { s1[wid] = sum; s2[wid] = sq; }
    __syncthreads();
    if (tid == 0) {
        float a = 0.0f, b2 = 0.0f;
        #pragma unroll
        for (int w = 0; w < 8; w++) { a += s1[w]; b2 += s2[w]; }
        s1[0] = a; s2[0] = b2;
    }
    __syncthreads();
    float mean = s1[0] * (1.0f / D);
    float var  = s2[0] * (1.0f / D) - mean * mean;
    float invs = rsqrtf(var + LN_EPS);
    y[n * D + j0]     = (o0 - mean) * invs * lng[j0]     + lnb[j0];
    y[n * D + j0 + 1] = (o1 - mean) * invs * lng[j0 + 1] + lnb[j0 + 1];
}

// ---------------- launch ----------------
extern "C" void kernel_launch(void* const* d_in, const int* in_sizes, int n_in,
                              void* d_out, int out_size)
{
    (void)in_sizes; (void)n_in; (void)out_size;
    const float* x   = (const float*)d_in[0];
    const float* wq  = (const float*)d_in[1];
    const float* bq  = (const float*)d_in[2];
    const float* wk  = (const float*)d_in[3];
    const float* bk  = (const float*)d_in[4];
    const float* wv  = (const float*)d_in[5];
    const float* bv  = (const float*)d_in[6];
    const float* wo  = (const float*)d_in[7];
    const float* bo  = (const float*)d_in[8];
    const float* g1w = (const float*)d_in[9];
    const float* g1b = (const float*)d_in[10];
    const float* g2w = (const float*)d_in[11];
    const float* g2b = (const float*)d_in[12];
    const float* lng = (const float*)d_in[13];
    const float* lnb = (const float*)d_in[14];

    float* y    = (float*)d_out;
    float* attn = y + (size_t)NB * D;

    const int SMEM_SC = (3 * 128 * 68 + 128 + 256) * (int)sizeof(float);      // 105984
    const int SMEM_AV = (128 * 68 + 64 * 72) * (int)sizeof(float);            // 53248
    cudaFuncSetAttribute(scores_kernel,
                         cudaFuncAttributeMaxDynamicSharedMemorySize, SMEM_SC);
    cudaFuncSetAttribute(attnv_kernel,
                         cudaFuncAttributeMaxDynamicSharedMemorySize, SMEM_AV);

    init_kernel<<<(BH * S + 255) / 256, 256>>>();
    qkv_mma_kernel<<<dim3(4, 32, 3), 256>>>(x, wq, bq, wk, bk, wv, bv);
    scores_kernel<<<dim3(16, 16, 16), 256, SMEM_SC>>>(attn);
    attnv_kernel<<<dim3(16, 16), 256, SMEM_AV>>>(attn);
    proj_mma_kernel<1><<<dim3(4, 32), 256>>>(nullptr, wo, bo, 512);
    proj_mma_kernel<2><<<dim3(2, 32), 256>>>(x, g1w, g1b, 256);
    gate_kernel<<<(NB * 32) / 256, 256>>>(g2w, g2b);
    ln_kernel<<<NB, 256>>>(x, lng, lnb, y);
}

// round 15
// speedup vs baseline: 1.4553x; 1.4553x over previous
#include <cuda_runtime.h>
#include <math.h>

namespace {
constexpr int B  = 2;
constexpr int S  = 2048;
constexpr int D  = 512;
constexpr int H  = 8;
constexpr int DK = 64;
constexpr int NB = B * S;
constexpr int BH = B * H;
constexpr int DH = D / 2;
constexpr float DECAY = 0.02f;
constexpr float LN_EPS = 1e-5f;
}

// ---------------- device scratch ----------------
__device__ float g_q[BH * S * DK];      // (b,h,s,dk)
__device__ float g_k[BH * S * DK];
__device__ float g_v[BH * S * DK];
__device__ float g_o[NB * D];           // token-major (n, h*64+dk)
__device__ float g_proj[NB * D];
__device__ float g_hidden[NB * DH];
__device__ float g_gate[NB];
__device__ float g_rowsum[BH * S];
__device__ float g_decay[S];

// ---------------- tf32 helpers ----------------
__device__ __forceinline__ unsigned cvt_tf32(float f) {
    unsigned u;
    asm("cvt.rna.tf32.f32 %0, %1;" : "=r"(u) : "f"(f));
    return u;
}
__device__ __forceinline__ void split_tf32(float a, unsigned &hi, unsigned &lo) {
    hi = cvt_tf32(a);
    lo = cvt_tf32(a - __uint_as_float(hi));
}
__device__ __forceinline__ void mma8(float (&c)[4], const unsigned (&a)[4],
                                     const unsigned (&b)[2]) {
    asm volatile(
        "mma.sync.aligned.m16n8k8.row.col.f32.tf32.tf32.f32 "
        "{%0,%1,%2,%3}, {%4,%5,%6,%7}, {%8,%9}, {%0,%1,%2,%3};"
        : "+f"(c[0]), "+f"(c[1]), "+f"(c[2]), "+f"(c[3])
        : "r"(a[0]), "r"(a[1]), "r"(a[2]), "r"(a[3]), "r"(b[0]), "r"(b[1]));
}

// ---------------- init ----------------
__global__ void init_kernel() {
    int idx = blockIdx.x * blockDim.x + threadIdx.x;
    if (idx < BH * S) g_rowsum[idx] = 0.0f;
    if (idx < S)      g_decay[idx] = expf(-DECAY * (float)idx);
}

// ---------------- tf32 GEMM core v2: pre-split 2-pass, 128x128 tile, BK=16 ----------------
__device__ __forceinline__ void gemm_core(
    const float* __restrict__ A, const float* __restrict__ W, int N,
    int row0, int col0, float* Ahi, float* Alo, float* Bs, float (&acc)[2][8][4])
{
    const int tid = threadIdx.x, lane = tid & 31, wid = tid >> 5;
    const int g = lane >> 2, t4 = lane & 3, wm = wid >> 1, wn = wid & 1;
    const int ar = tid >> 1, ak = (tid & 1) * 8;
    const int bk = tid >> 4, bc = (tid & 15) * 4;

    const float* Ap = A + (size_t)(row0 + ar) * 512 + ak;
    const float* Wp = W + (size_t)bk * N + col0 + bc;

    float4 ra0 = *(const float4*)Ap, ra1 = *(const float4*)(Ap + 4);
    float4 rb0 = *(const float4*)Wp, rb1 = *(const float4*)(Wp + 64);

    for (int k0 = 0; k0 < 512; k0 += 16) {
        {
            unsigned h0, l0, h1, l1, h2, l2, h3, l3;
            split_tf32(ra0.x, h0, l0); split_tf32(ra0.y, h1, l1);
            split_tf32(ra0.z, h2, l2); split_tf32(ra0.w, h3, l3);
            *(float4*)&Ahi[ar * 20 + ak] = make_float4(
                __uint_as_float(h0), __uint_as_float(h1),
                __uint_as_float(h2), __uint_as_float(h3));
            *(float4*)&Alo[ar * 20 + ak] = make_float4(
                __uint_as_float(l0), __uint_as_float(l1),
                __uint_as_float(l2), __uint_as_float(l3));
            split_tf32(ra1.x, h0, l0); split_tf32(ra1.y, h1, l1);
            split_tf32(ra1.z, h2, l2); split_tf32(ra1.w, h3, l3);
            *(float4*)&Ahi[ar * 20 + ak + 4] = make_float4(
                __uint_as_float(h0), __uint_as_float(h1),
                __uint_as_float(h2), __uint_as_float(h3));
            *(float4*)&Alo[ar * 20 + ak + 4] = make_float4(
                __uint_as_float(l0), __uint_as_float(l1),
                __uint_as_float(l2), __uint_as_float(l3));
        }
        *(float4*)&Bs[bk * 132 + bc] = make_float4(
            __uint_as_float(cvt_tf32(rb0.x)), __uint_as_float(cvt_tf32(rb0.y)),
            __uint_as_float(cvt_tf32(rb0.z)), __uint_as_float(cvt_tf32(rb0.w)));
        *(float4*)&Bs[bk * 132 + bc + 64] = make_float4(
            __uint_as_float(cvt_tf32(rb1.x)), __uint_as_float(cvt_tf32(rb1.y)),
            __uint_as_float(cvt_tf32(rb1.z)), __uint_as_float(cvt_tf32(rb1.w)));
        __syncthreads();
        if (k0 + 16 < 512) {
            ra0 = *(const float4*)(Ap + k0 + 16);
            ra1 = *(const float4*)(Ap + k0 + 20);
            const float* w2 = Wp + (size_t)(k0 + 16) * N;
            rb0 = *(const float4*)w2;
            rb1 = *(const float4*)(w2 + 64);
        }
        #pragma unroll
        for (int ks = 0; ks < 2; ks++) {
            const int kk = ks * 8;
            unsigned ahi[2][4], alo[2][4], bb[8][2];
            #pragma unroll
            for (int mt = 0; mt < 2; mt++) {
                int base = (wm * 32 + mt * 16 + g) * 20 + kk;
                ahi[mt][0] = __float_as_uint(Ahi[base + t4]);
                ahi[mt][1] = __float_as_uint(Ahi[base + 8 * 20 + t4]);
                ahi[mt][2] = __float_as_uint(Ahi[base + t4 + 4]);
                ahi[mt][3] = __float_as_uint(Ahi[base + 8 * 20 + t4 + 4]);
                alo[mt][0] = __float_as_uint(Alo[base + t4]);
                alo[mt][1] = __float_as_uint(Alo[base + 8 * 20 + t4]);
                alo[mt][2] = __float_as_uint(Alo[base + t4 + 4]);
                alo[mt][3] = __float_as_uint(Alo[base + 8 * 20 + t4 + 4]);
            }
            #pragma unroll
            for (int nt = 0; nt < 8; nt++) {
                int n = wn * 64 + nt * 8 + g;
                bb[nt][0] = __float_as_uint(Bs[(kk + t4) * 132 + n]);
                bb[nt][1] = __float_as_uint(Bs[(kk + t4 + 4) * 132 + n]);
            }
            #pragma unroll
            for (int mt = 0; mt < 2; mt++)
                #pragma unroll
                for (int nt = 0; nt < 8; nt++)
                    mma8(acc[mt][nt], ahi[mt], bb[nt]);
            #pragma unroll
            for (int mt = 0; mt < 2; mt++)
                #pragma unroll
                for (int nt = 0; nt < 8; nt++)
                    mma8(acc[mt][nt], alo[mt], bb[nt]);
        }
        __syncthreads();
    }
}

// ---------------- QKV projection via mma ----------------
__global__ __launch_bounds__(256, 2) void qkv_mma_kernel(
    const float* __restrict__ x,
    const float* __restrict__ wq, const float* __restrict__ bq,
    const float* __restrict__ wk, const float* __restrict__ bk_,
    const float* __restrict__ wv, const float* __restrict__ bv)
{
    __shared__ __align__(16) float Ahi[128 * 20];
    __shared__ __align__(16) float Alo[128 * 20];
    __shared__ __align__(16) float Bs[16 * 132];

    const float* W; const float* bias; float* out;
    if (blockIdx.z == 0)      { W = wq; bias = bq;  out = g_q; }
    else if (blockIdx.z == 1) { W = wk; bias = bk_; out = g_k; }
    else                      { W = wv; bias = bv;  out = g_v; }

    const int row0 = blockIdx.y * 128, col0 = blockIdx.x * 128;
    float acc[2][8][4] = {};
    gemm_core(x, W, 512, row0, col0, Ahi, Alo, Bs, acc);

    const int tid = threadIdx.x, lane = tid & 31, wid = tid >> 5;
    const int g = lane >> 2, t4 = lane & 3, wm = wid >> 1, wn = wid & 1;

    #pragma unroll
    for (int mt = 0; mt < 2; mt++) {
        int n0 = row0 + wm * 32 + mt * 16 + g;
        int n1 = n0 + 8;
        int b0i = n0 >> 11, s0 = n0 & 2047;
        int b1i = n1 >> 11, s1 = n1 & 2047;
        #pragma unroll
        for (int nt = 0; nt < 8; nt++) {
            int c0 = col0 + wn * 64 + nt * 8 + 2 * t4;
            int h = c0 >> 6, dk = c0 & 63;
            float bb0 = bias[c0], bb1 = bias[c0 + 1];
            *(float2*)&out[(((size_t)(b0i * H + h)) * S + s0) * DK + dk] =
                make_float2(acc[mt][nt][0] + bb0, acc[mt][nt][1] + bb1);
            *(float2*)&out[(((size_t)(b1i * H + h)) * S + s1) * DK + dk] =
                make_float2(acc[mt][nt][2] + bb0, acc[mt][nt][3] + bb1);
        }
    }
}

// ---------------- generic projection via mma (1: oproj, 2: hidden+relu) ----------------
template<int MODE>
__global__ __launch_bounds__(256, 2) void proj_mma_kernel(
    const float* __restrict__ Ain, const float* __restrict__ W,
    const float* __restrict__ bias, int N)
{
    __shared__ __align__(16) float Ahi[128 * 20];
    __shared__ __align__(16) float Alo[128 * 20];
    __shared__ __align__(16) float Bs[16 * 132];

    const float* A = (MODE == 1) ? g_o : Ain;
    float* C = (MODE == 1) ? g_proj : g_hidden;

    const int row0 = blockIdx.y * 128, col0 = blockIdx.x * 128;
    float acc[2][8][4] = {};
    gemm_core(A, W, N, row0, col0, Ahi, Alo, Bs, acc);

    const int tid = threadIdx.x, lane = tid & 31, wid = tid >> 5;
    const int g = lane >> 2, t4 = lane & 3, wm = wid >> 1, wn = wid & 1;

    #pragma unroll
    for (int mt = 0; mt < 2; mt++) {
        int n0 = row0 + wm * 32 + mt * 16 + g;
        int n1 = n0 + 8;
        #pragma unroll
        for (int nt = 0; nt < 8; nt++) {
            int c0 = col0 + wn * 64 + nt * 8 + 2 * t4;
            float bb0 = bias[c0], bb1 = bias[c0 + 1];
            float v0 = acc[mt][nt][0] + bb0, v1 = acc[mt][nt][1] + bb1;
            float v2 = acc[mt][nt][2] + bb0, v3 = acc[mt][nt][3] + bb1;
            if (MODE == 2) {
                v0 = fmaxf(v0, 0.0f); v1 = fmaxf(v1, 0.0f);
                v2 = fmaxf(v2, 0.0f); v3 = fmaxf(v3, 0.0f);
            }
            *(float2*)&C[(size_t)n0 * N + c0] = make_float2(v0, v1);
            *(float2*)&C[(size_t)n1 * N + c0] = make_float2(v2, v3);
        }
    }
}

// ---------------- scores: 1-pass tf32 mma (Q single), pre-cvt smem, decay window ----------------
// Smem floats: Qs[128*68] + Kt[128*68] + ssum[128] + dwin[256] = 17792 (71168 B).
__global__ __launch_bounds__(256, 2) void scores_kernel(float* __restrict__ attn)
{
    extern __shared__ __align__(16) float sm[];
    float* Qs = sm;
    float* Kt  = sm + 128 * 68;
    float* ssum = sm + 2 * 128 * 68;
    float* dwin = ssum + 128;

    const int bh = blockIdx.z;
    const int row0 = blockIdx.y * 128;
    const int col0 = blockIdx.x * 128;
    const int tid = threadIdx.x, lane = tid & 31, wid = tid >> 5;
    const int g = lane >> 2, t4 = lane & 3, wm = wid >> 1, wn = wid & 1;

    const float* qb = g_q + ((size_t)bh * S + row0) * DK;
    const float* kb = g_k + ((size_t)bh * S + col0) * DK;

    #pragma unroll
    for (int i = 0; i < 8; i++) {
        int lin = i * 256 + tid;
        int r = lin >> 4, c4 = (lin & 15) * 4;
        float4 qv = *(const float4*)&qb[r * DK + c4];
        float4 kv = *(const float4*)&kb[r * DK + c4];
        *(float4*)&Qs[r * 68 + c4] = make_float4(
            __uint_as_float(cvt_tf32(qv.x)), __uint_as_float(cvt_tf32(qv.y)),
            __uint_as_float(cvt_tf32(qv.z)), __uint_as_float(cvt_tf32(qv.w)));
        *(float4*)&Kt[r * 68 + c4] = make_float4(
            __uint_as_float(cvt_tf32(kv.x)), __uint_as_float(cvt_tf32(kv.y)),
            __uint_as_float(cvt_tf32(kv.z)), __uint_as_float(cvt_tf32(kv.w)));
    }
    if (tid < 128) ssum[tid] = 0.0f;
    {
        int d = row0 - col0 - 127 + tid;
        dwin[tid] = (d >= 0 && d < S) ? g_decay[d] : 0.0f;
    }
    __syncthreads();

    float acc[2][8][4] = {};
    #pragma unroll
    for (int ks = 0; ks < 8; ks++) {
        const int kk = ks * 8;
        unsigned ahi[2][4], bb[8][2];
        #pragma unroll
        for (int mt = 0; mt < 2; mt++) {
            int base = (wm * 32 + mt * 16 + g) * 68 + kk;
            ahi[mt][0] = __float_as_uint(Qs[base + t4]);
            ahi[mt][1] = __float_as_uint(Qs[base + 8 * 68 + t4]);
            ahi[mt][2] = __float_as_uint(Qs[base + t4 + 4]);
            ahi[mt][3] = __float_as_uint(Qs[base + 8 * 68 + t4 + 4]);
        }
        #pragma unroll
        for (int nt = 0; nt < 8; nt++) {
            int n = wn * 64 + nt * 8 + g;
            bb[nt][0] = __float_as_uint(Kt[n * 68 + kk + t4]);
            bb[nt][1] = __float_as_uint(Kt[n * 68 + kk + t4 + 4]);
        }
        #pragma unroll
        for (int mt = 0; mt < 2; mt++)
            #pragma unroll
            for (int nt = 0; nt < 8; nt++)
                mma8(acc[mt][nt], ahi[mt], bb[nt]);
    }

    float rsum[2][2] = {};
    #pragma unroll
    for (int mt = 0; mt < 2; mt++) {
        int rl = wm * 32 + mt * 16 + g;
        int gi0 = row0 + rl, gi1 = gi0 + 8;
        #pragma unroll
        for (int nt = 0; nt < 8; nt++) {
            int cl = wn * 64 + nt * 8 + 2 * t4;
            int gj = col0 + cl;
            int ib = rl - cl + 127;
            float v0 = acc[mt][nt][0] * 0.125f + dwin[ib];
            float v1 = acc[mt][nt][1] * 0.125f + dwin[ib - 1];
            float v2 = acc[mt][nt][2] * 0.125f + dwin[ib + 8];
            float v3 = acc[mt][nt][3] * 0.125f + dwin[ib + 7];
            float p0 = __expf(v0), p1 = __expf(v1);
            float p2 = __expf(v2), p3 = __expf(v3);
            rsum[mt][0] += p0 + p1;
            rsum[mt][1] += p2 + p3;
            *(float2*)&attn[((size_t)bh * S + gi0) * S + gj] = make_float2(p0, p1);
            *(float2*)&attn[((size_t)bh * S + gi1) * S + gj] = make_float2(p2, p3);
        }
    }
    #pragma unroll
    for (int mt = 0; mt < 2; mt++)
        #pragma unroll
        for (int h2 = 0; h2 < 2; h2++) {
            float v = rsum[mt][h2];
            v += __shfl_xor_sync(0xffffffffu, v, 1);
            v += __shfl_xor_sync(0xffffffffu, v, 2);
            if (t4 == 0) atomicAdd(&ssum[wm * 32 + mt * 16 + h2 * 8 + g], v);
        }
    __syncthreads();
    if (tid < 128) atomicAdd(&g_rowsum[(size_t)bh * S + row0 + tid], ssum[tid]);
}

// ---------------- attn@V: pipelined (register prefetch) + in-place normalize (R9 winner) ----------------
__global__ __launch_bounds__(256, 2) void attnv_kernel(float* __restrict__ attn)
{
    extern __shared__ __align__(16) float sm[];
    float* Phi = sm;
    float* Plo = sm + 128 * 68;
    float* Vt  = sm + 2 * 128 * 68;

    const int bh = blockIdx.y, row0 = blockIdx.x * 128;
    const int bb = bh >> 3, hh = bh & 7;
    const int tid = threadIdx.x, lane = tid & 31, wid = tid >> 5;
    const int g = lane >> 2, t4 = lane & 3, wm = wid >> 1, wn = wid & 1;

    const int r_p = tid >> 4;
    const int c4 = (tid & 15) * 4;

    float* gp0 = attn + ((size_t)bh * S + row0 + r_p) * S + c4;
    const float* vp0 = g_v + ((size_t)bh * S + r_p) * DK + c4;

    float invr[8];
    #pragma unroll
    for (int i = 0; i < 8; i++)
        invr[i] = 1.0f / g_rowsum[(size_t)bh * S + row0 + i * 16 + r_p];

    float acc[2][4][4] = {};

    float4 pv[8], vv[4];
    #pragma unroll
    for (int i = 0; i < 8; i++) pv[i] = *(const float4*)(gp0 + (size_t)i * 16 * S);
    #pragma unroll
    for (int i = 0; i < 4; i++) vv[i] = *(const float4*)(vp0 + i * 16 * DK);

    for (int kt = 0; kt < 32; kt++) {
        #pragma unroll
        for (int i = 0; i < 8; i++) {
            int r = i * 16 + r_p;
            float4 a = pv[i];
            float inv = invr[i];
            a.x *= inv; a.y *= inv; a.z *= inv; a.w *= inv;
            *(float4*)(gp0 + (size_t)i * 16 * S) = a;
            unsigned h0, l0, h1, l1, h2, l2, h3, l3;
            split_tf32(a.x, h0, l0); split_tf32(a.y, h1, l1);
            split_tf32(a.z, h2, l2); split_tf32(a.w, h3, l3);
            *(float4*)&Phi[r * 68 + c4] = make_float4(
                __uint_as_float(h0), __uint_as_float(h1),
                __uint_as_float(h2), __uint_as_float(h3));
            *(float4*)&Plo[r * 68 + c4] = make_float4(
                __uint_as_float(l0), __uint_as_float(l1),
                __uint_as_float(l2), __uint_as_float(l3));
        }
        #pragma unroll
        for (int i = 0; i < 4; i++) {
            int r = i * 16 + r_p;
            *(float4*)&Vt[r * 72 + c4] = make_float4(
                __uint_as_float(cvt_tf32(vv[i].x)), __uint_as_float(cvt_tf32(vv[i].y)),
                __uint_as_float(cvt_tf32(vv[i].z)), __uint_as_float(cvt_tf32(vv[i].w)));
        }
        gp0 += 64;
        __syncthreads();

        if (kt + 1 < 32) {
            #pragma unroll
            for (int i = 0; i < 8; i++)
                pv[i] = *(const float4*)(gp0 + (size_t)i * 16 * S);
            const float* vp = vp0 + (size_t)(kt + 1) * 64 * DK;
            #pragma unroll
            for (int i = 0; i < 4; i++)
                vv[i] = *(const float4*)(vp + i * 16 * DK);
        }

        #pragma unroll
        for (int ks = 0; ks < 8; ks++) {
            const int kk = ks * 8;
            unsigned ahi[2][4], alo[2][4], bb2[4][2];
            #pragma unroll
            for (int mt = 0; mt < 2; mt++) {
                int base = (wm * 32 + mt * 16 + g) * 68 + kk;
                ahi[mt][0] = __float_as_uint(Phi[base + t4]);
                ahi[mt][1] = __float_as_uint(Phi[base + 8 * 68 + t4]);
                ahi[mt][2] = __float_as_uint(Phi[base + t4 + 4]);
                ahi[mt][3] = __float_as_uint(Phi[base + 8 * 68 + t4 + 4]);
                alo[mt][0] = __float_as_uint(Plo[base + t4]);
                alo[mt][1] = __float_as_uint(Plo[base + 8 * 68 + t4]);
                alo[mt][2] = __float_as_uint(Plo[base + t4 + 4]);
                alo[mt][3] = __float_as_uint(Plo[base + 8 * 68 + t4 + 4]);
            }
            #pragma unroll
            for (int nt = 0; nt < 4; nt++) {
                int n = wn * 32 + nt * 8 + g;
                bb2[nt][0] = __float_as_uint(Vt[(kk + t4) * 72 + n]);
                bb2[nt][1] = __float_as_uint(Vt[(kk + t4 + 4) * 72 + n]);
            }
            #pragma unroll
            for (int mt = 0; mt < 2; mt++)
                #pragma unroll
                for (int nt = 0; nt < 4; nt++)
                    mma8(acc[mt][nt], ahi[mt], bb2[nt]);
            #pragma unroll
            for (int mt = 0; mt < 2; mt++)
                #pragma unroll
                for (int nt = 0; nt < 4; nt++)
                    mma8(acc[mt][nt], alo[mt], bb2[nt]);
        }
        __syncthreads();
    }

    #pragma unroll
    for (int mt = 0; mt < 2; mt++) {
        int rl = wm * 32 + mt * 16 + g;
        size_t tok0 = (size_t)bb * S + row0 + rl;
        size_t tok1 = tok0 + 8;
        #pragma unroll
        for (int nt = 0; nt < 4; nt++) {
            int dk = wn * 32 + nt * 8 + 2 * t4;
            *(float2*)&g_o[tok0 * D + hh * 64 + dk] =
                make_float2(acc[mt][nt][0], acc[mt][nt][1]);
            *(float2*)&g_o[tok1 * D + hh * 64 + dk] =
                make_float2(acc[mt][nt][2], acc[mt][nt][3]);
        }
    }
}

// ---------------- gate scalar ----------------
__global__ void gate_kernel(const float* __restrict__ g2w,
                            const float* __restrict__ g2b)
{
    int warp = (blockIdx.x * blockDim.x + threadIdx.x) >> 5;
    int lane = threadIdx.x & 31;
    if (warp >= NB) return;
    float sum = 0.0f;
    #pragma unroll
    for (int i = 0; i < DH / 32; i++)
        sum += g_hidden[warp * DH + i * 32 + lane] * g2w[i * 32 + lane];
    #pragma unroll
    for (int off = 16; off; off >>= 1)
        sum += __shfl_down_sync(0xffffffffu, sum, off);
    if (lane == 0)
        g_gate[warp] = 1.0f / (1.0f + expf(-(sum + g2b[0])));
}

// ---------------- gated residual + LayerNorm ----------------
__global__ __launch_bounds__(256) void ln_kernel(
    const float* __restrict__ x,
    const float* __restrict__ lng, const float* __restrict__ lnb,
    float* __restrict__ y)
{
    __shared__ float s1[8], s2[8];
    const int n = blockIdx.x;
    const int tid = threadIdx.x;
    const float g = g_gate[n];

    int j0 = tid * 2;
    float2 pr = *(const float2*)&g_proj[n * D + j0];
    float2 xr = *(const float2*)&x[n * D + j0];
    float o0 = pr.x * g + xr.x * (1.0f - g);
    float o1 = pr.y * g + xr.y * (1.0f - g);

    float sum = o0 + o1, sq = o0 * o0 + o1 * o1;
    #pragma unroll
    for (int off = 16; off; off >>= 1) {
        sum += __shfl_down_sync(0xffffffffu, sum, off);
        sq  += __shfl_down_sync(0xffffffffu, sq,  off);
    }
    int wid = tid >> 5, lane = tid & 31;
    if (lane == 0) { s1[wid] = sum; s2[wid] = sq; }
    __syncthreads();
    if (tid == 0) {
        float a = 0.0f, b2 = 0.0f;
        #pragma unroll
        for (int w = 0; w < 8; w++) { a += s1[w]; b2 += s2[w]; }
        s1[0] = a; s2[0] = b2;
    }
    __syncthreads();
    float mean = s1[0] * (1.0f / D);
    float var  = s2[0] * (1.0f / D) - mean * mean;
    float invs = rsqrtf(var + LN_EPS);
    y[n * D + j0]     = (o0 - mean) * invs * lng[j0]     + lnb[j0];
    y[n * D + j0 + 1] = (o1 - mean) * invs * lng[j0 + 1] + lnb[j0 + 1];
}

// ---------------- launch ----------------
extern "C" void kernel_launch(void* const* d_in, const int* in_sizes, int n_in,
                              void* d_out, int out_size)
{
    (void)in_sizes; (void)n_in; (void)out_size;
    const float* x   = (const float*)d_in[0];
    const float* wq  = (const float*)d_in[1];
    const float* bq  = (const float*)d_in[2];
    const float* wk  = (const float*)d_in[3];
    const float* bk  = (const float*)d_in[4];
    const float* wv  = (const float*)d_in[5];
    const float* bv  = (const float*)d_in[6];
    const float* wo  = (const float*)d_in[7];
    const float* bo  = (const float*)d_in[8];
    const float* g1w = (const float*)d_in[9];
    const float* g1b = (const float*)d_in[10];
    const float* g2w = (const float*)d_in[11];
    const float* g2b = (const float*)d_in[12];
    const float* lng = (const float*)d_in[13];
    const float* lnb = (const float*)d_in[14];

    float* y    = (float*)d_out;
    float* attn = y + (size_t)NB * D;

    const int SMEM_SC = (2 * 128 * 68 + 128 + 256) * (int)sizeof(float);      // 71168
    const int SMEM_AV = (2 * 128 * 68 + 64 * 72) * (int)sizeof(float);        // 88064
    cudaFuncSetAttribute(scores_kernel,
                         cudaFuncAttributeMaxDynamicSharedMemorySize, SMEM_SC);
    cudaFuncSetAttribute(attnv_kernel,
                         cudaFuncAttributeMaxDynamicSharedMemorySize, SMEM_AV);

    init_kernel<<<(BH * S + 255) / 256, 256>>>();
    qkv_mma_kernel<<<dim3(4, 32, 3), 256>>>(x, wq, bq, wk, bk, wv, bv);
    scores_kernel<<<dim3(16, 16, 16), 256, SMEM_SC>>>(attn);
    attnv_kernel<<<dim3(16, 16), 256, SMEM_AV>>>(attn);
    proj_mma_kernel<1><<<dim3(4, 32), 256>>>(nullptr, wo, bo, 512);
    proj_mma_kernel<2><<<dim3(2, 32), 256>>>(x, g1w, g1b, 256);
    gate_kernel<<<(NB * 32) / 256, 256>>>(g2w, g2b);
    ln_kernel<<<NB, 256>>>(x, lng, lnb, y);
}

// round 16
// speedup vs baseline: 1.6968x; 1.1660x over previous
#include <cuda_runtime.h>
#include <math.h>

namespace {
constexpr int B  = 2;
constexpr int S  = 2048;
constexpr int D  = 512;
constexpr int H  = 8;
constexpr int DK = 64;
constexpr int NB = B * S;
constexpr int BH = B * H;
constexpr int DH = D / 2;
constexpr float DECAY = 0.02f;
constexpr float LN_EPS = 1e-5f;
}

// ---------------- device scratch ----------------
__device__ float g_q[BH * S * DK];      // (b,h,s,dk)
__device__ float g_k[BH * S * DK];
__device__ float g_v[BH * S * DK];
__device__ float g_o[NB * D];           // token-major (n, h*64+dk)
__device__ float g_proj[NB * D];
__device__ float g_hidden[NB * DH];
__device__ float g_gate[NB];
__device__ float g_rowsum[BH * S];
__device__ float g_decay[S];

// ---------------- tf32 helpers ----------------
__device__ __forceinline__ unsigned cvt_tf32(float f) {
    unsigned u;
    asm("cvt.rna.tf32.f32 %0, %1;" : "=r"(u) : "f"(f));
    return u;
}
__device__ __forceinline__ void split_tf32(float a, unsigned &hi, unsigned &lo) {
    hi = cvt_tf32(a);
    lo = cvt_tf32(a - __uint_as_float(hi));
}
__device__ __forceinline__ void mma8(float (&c)[4], const unsigned (&a)[4],
                                     const unsigned (&b)[2]) {
    asm volatile(
        "mma.sync.aligned.m16n8k8.row.col.f32.tf32.tf32.f32 "
        "{%0,%1,%2,%3}, {%4,%5,%6,%7}, {%8,%9}, {%0,%1,%2,%3};"
        : "+f"(c[0]), "+f"(c[1]), "+f"(c[2]), "+f"(c[3])
        : "r"(a[0]), "r"(a[1]), "r"(a[2]), "r"(a[3]), "r"(b[0]), "r"(b[1]));
}

// ---------------- init ----------------
__global__ void init_kernel() {
    int idx = blockIdx.x * blockDim.x + threadIdx.x;
    if (idx < BH * S) g_rowsum[idx] = 0.0f;
    if (idx < S)      g_decay[idx] = expf(-DECAY * (float)idx);
}

// ---------------- tf32 GEMM core v3: single-tf32 A, 1-pass, 128x128 tile, BK=16 ----------------
// Smem floats: As 2560 + Bs 2112 = 4672 (18688 B).
__device__ __forceinline__ void gemm_core(
    const float* __restrict__ A, const float* __restrict__ W, int N,
    int row0, int col0, float* As, float* Bs, float (&acc)[2][8][4])
{
    const int tid = threadIdx.x, lane = tid & 31, wid = tid >> 5;
    const int g = lane >> 2, t4 = lane & 3, wm = wid >> 1, wn = wid & 1;
    const int ar = tid >> 1, ak = (tid & 1) * 8;
    const int bk = tid >> 4, bc = (tid & 15) * 4;

    const float* Ap = A + (size_t)(row0 + ar) * 512 + ak;
    const float* Wp = W + (size_t)bk * N + col0 + bc;

    float4 ra0 = *(const float4*)Ap, ra1 = *(const float4*)(Ap + 4);
    float4 rb0 = *(const float4*)Wp, rb1 = *(const float4*)(Wp + 64);

    for (int k0 = 0; k0 < 512; k0 += 16) {
        *(float4*)&As[ar * 20 + ak] = make_float4(
            __uint_as_float(cvt_tf32(ra0.x)), __uint_as_float(cvt_tf32(ra0.y)),
            __uint_as_float(cvt_tf32(ra0.z)), __uint_as_float(cvt_tf32(ra0.w)));
        *(float4*)&As[ar * 20 + ak + 4] = make_float4(
            __uint_as_float(cvt_tf32(ra1.x)), __uint_as_float(cvt_tf32(ra1.y)),
            __uint_as_float(cvt_tf32(ra1.z)), __uint_as_float(cvt_tf32(ra1.w)));
        *(float4*)&Bs[bk * 132 + bc] = make_float4(
            __uint_as_float(cvt_tf32(rb0.x)), __uint_as_float(cvt_tf32(rb0.y)),
            __uint_as_float(cvt_tf32(rb0.z)), __uint_as_float(cvt_tf32(rb0.w)));
        *(float4*)&Bs[bk * 132 + bc + 64] = make_float4(
            __uint_as_float(cvt_tf32(rb1.x)), __uint_as_float(cvt_tf32(rb1.y)),
            __uint_as_float(cvt_tf32(rb1.z)), __uint_as_float(cvt_tf32(rb1.w)));
        __syncthreads();
        if (k0 + 16 < 512) {
            ra0 = *(const float4*)(Ap + k0 + 16);
            ra1 = *(const float4*)(Ap + k0 + 20);
            const float* w2 = Wp + (size_t)(k0 + 16) * N;
            rb0 = *(const float4*)w2;
            rb1 = *(const float4*)(w2 + 64);
        }
        #pragma unroll
        for (int ks = 0; ks < 2; ks++) {
            const int kk = ks * 8;
            unsigned ahi[2][4], bb[8][2];
            #pragma unroll
            for (int mt = 0; mt < 2; mt++) {
                int base = (wm * 32 + mt * 16 + g) * 20 + kk;
                ahi[mt][0] = __float_as_uint(As[base + t4]);
                ahi[mt][1] = __float_as_uint(As[base + 8 * 20 + t4]);
                ahi[mt][2] = __float_as_uint(As[base + t4 + 4]);
                ahi[mt][3] = __float_as_uint(As[base + 8 * 20 + t4 + 4]);
            }
            #pragma unroll
            for (int nt = 0; nt < 8; nt++) {
                int n = wn * 64 + nt * 8 + g;
                bb[nt][0] = __float_as_uint(Bs[(kk + t4) * 132 + n]);
                bb[nt][1] = __float_as_uint(Bs[(kk + t4 + 4) * 132 + n]);
            }
            #pragma unroll
            for (int mt = 0; mt < 2; mt++)
                #pragma unroll
                for (int nt = 0; nt < 8; nt++)
                    mma8(acc[mt][nt], ahi[mt], bb[nt]);
        }
        __syncthreads();
    }
}

// ---------------- QKV projection via mma ----------------
__global__ __launch_bounds__(256, 2) void qkv_mma_kernel(
    const float* __restrict__ x,
    const float* __restrict__ wq, const float* __restrict__ bq,
    const float* __restrict__ wk, const float* __restrict__ bk_,
    const float* __restrict__ wv, const float* __restrict__ bv)
{
    __shared__ __align__(16) float As[128 * 20];
    __shared__ __align__(16) float Bs[16 * 132];

    const float* W; const float* bias; float* out;
    if (blockIdx.z == 0)      { W = wq; bias = bq;  out = g_q; }
    else if (blockIdx.z == 1) { W = wk; bias = bk_; out = g_k; }
    else                      { W = wv; bias = bv;  out = g_v; }

    const int row0 = blockIdx.y * 128, col0 = blockIdx.x * 128;
    float acc[2][8][4] = {};
    gemm_core(x, W, 512, row0, col0, As, Bs, acc);

    const int tid = threadIdx.x, lane = tid & 31, wid = tid >> 5;
    const int g = lane >> 2, t4 = lane & 3, wm = wid >> 1, wn = wid & 1;

    #pragma unroll
    for (int mt = 0; mt < 2; mt++) {
        int n0 = row0 + wm * 32 + mt * 16 + g;
        int n1 = n0 + 8;
        int b0i = n0 >> 11, s0 = n0 & 2047;
        int b1i = n1 >> 11, s1 = n1 & 2047;
        #pragma unroll
        for (int nt = 0; nt < 8; nt++) {
            int c0 = col0 + wn * 64 + nt * 8 + 2 * t4;
            int h = c0 >> 6, dk = c0 & 63;
            float bb0 = bias[c0], bb1 = bias[c0 + 1];
            *(float2*)&out[(((size_t)(b0i * H + h)) * S + s0) * DK + dk] =
                make_float2(acc[mt][nt][0] + bb0, acc[mt][nt][1] + bb1);
            *(float2*)&out[(((size_t)(b1i * H + h)) * S + s1) * DK + dk] =
                make_float2(acc[mt][nt][2] + bb0, acc[mt][nt][3] + bb1);
        }
    }
}

// ---------------- generic projection via mma (1: oproj, 2: hidden+relu) ----------------
template<int MODE>
__global__ __launch_bounds__(256, 2) void proj_mma_kernel(
    const float* __restrict__ Ain, const float* __restrict__ W,
    const float* __restrict__ bias, int N)
{
    __shared__ __align__(16) float As[128 * 20];
    __shared__ __align__(16) float Bs[16 * 132];

    const float* A = (MODE == 1) ? g_o : Ain;
    float* C = (MODE == 1) ? g_proj : g_hidden;

    const int row0 = blockIdx.y * 128, col0 = blockIdx.x * 128;
    float acc[2][8][4] = {};
    gemm_core(A, W, N, row0, col0, As, Bs, acc);

    const int tid = threadIdx.x, lane = tid & 31, wid = tid >> 5;
    const int g = lane >> 2, t4 = lane & 3, wm = wid >> 1, wn = wid & 1;

    #pragma unroll
    for (int mt = 0; mt < 2; mt++) {
        int n0 = row0 + wm * 32 + mt * 16 + g;
        int n1 = n0 + 8;
        #pragma unroll
        for (int nt = 0; nt < 8; nt++) {
            int c0 = col0 + wn * 64 + nt * 8 + 2 * t4;
            float bb0 = bias[c0], bb1 = bias[c0 + 1];
            float v0 = acc[mt][nt][0] + bb0, v1 = acc[mt][nt][1] + bb1;
            float v2 = acc[mt][nt][2] + bb0, v3 = acc[mt][nt][3] + bb1;
            if (MODE == 2) {
                v0 = fmaxf(v0, 0.0f); v1 = fmaxf(v1, 0.0f);
                v2 = fmaxf(v2, 0.0f); v3 = fmaxf(v3, 0.0f);
            }
            *(float2*)&C[(size_t)n0 * N + c0] = make_float2(v0, v1);
            *(float2*)&C[(size_t)n1 * N + c0] = make_float2(v2, v3);
        }
    }
}

// ---------------- scores: 1-pass tf32 mma (Q single), pre-cvt smem, decay window ----------------
__global__ __launch_bounds__(256, 2) void scores_kernel(float* __restrict__ attn)
{
    extern __shared__ __align__(16) float sm[];
    float* Qs = sm;
    float* Kt  = sm + 128 * 68;
    float* ssum = sm + 2 * 128 * 68;
    float* dwin = ssum + 128;

    const int bh = blockIdx.z;
    const int row0 = blockIdx.y * 128;
    const int col0 = blockIdx.x * 128;
    const int tid = threadIdx.x, lane = tid & 31, wid = tid >> 5;
    const int g = lane >> 2, t4 = lane & 3, wm = wid >> 1, wn = wid & 1;

    const float* qb = g_q + ((size_t)bh * S + row0) * DK;
    const float* kb = g_k + ((size_t)bh * S + col0) * DK;

    #pragma unroll
    for (int i = 0; i < 8; i++) {
        int lin = i * 256 + tid;
        int r = lin >> 4, c4 = (lin & 15) * 4;
        float4 qv = *(const float4*)&qb[r * DK + c4];
        float4 kv = *(const float4*)&kb[r * DK + c4];
        *(float4*)&Qs[r * 68 + c4] = make_float4(
            __uint_as_float(cvt_tf32(qv.x)), __uint_as_float(cvt_tf32(qv.y)),
            __uint_as_float(cvt_tf32(qv.z)), __uint_as_float(cvt_tf32(qv.w)));
        *(float4*)&Kt[r * 68 + c4] = make_float4(
            __uint_as_float(cvt_tf32(kv.x)), __uint_as_float(cvt_tf32(kv.y)),
            __uint_as_float(cvt_tf32(kv.z)), __uint_as_float(cvt_tf32(kv.w)));
    }
    if (tid < 128) ssum[tid] = 0.0f;
    {
        int d = row0 - col0 - 127 + tid;
        dwin[tid] = (d >= 0 && d < S) ? g_decay[d] : 0.0f;
    }
    __syncthreads();

    float acc[2][8][4] = {};
    #pragma unroll
    for (int ks = 0; ks < 8; ks++) {
        const int kk = ks * 8;
        unsigned ahi[2][4], bb[8][2];
        #pragma unroll
        for (int mt = 0; mt < 2; mt++) {
            int base = (wm * 32 + mt * 16 + g) * 68 + kk;
            ahi[mt][0] = __float_as_uint(Qs[base + t4]);
            ahi[mt][1] = __float_as_uint(Qs[base + 8 * 68 + t4]);
            ahi[mt][2] = __float_as_uint(Qs[base + t4 + 4]);
            ahi[mt][3] = __float_as_uint(Qs[base + 8 * 68 + t4 + 4]);
        }
        #pragma unroll
        for (int nt = 0; nt < 8; nt++) {
            int n = wn * 64 + nt * 8 + g;
            bb[nt][0] = __float_as_uint(Kt[n * 68 + kk + t4]);
            bb[nt][1] = __float_as_uint(Kt[n * 68 + kk + t4 + 4]);
        }
        #pragma unroll
        for (int mt = 0; mt < 2; mt++)
            #pragma unroll
            for (int nt = 0; nt < 8; nt++)
                mma8(acc[mt][nt], ahi[mt], bb[nt]);
    }

    float rsum[2][2] = {};
    #pragma unroll
    for (int mt = 0; mt < 2; mt++) {
        int rl = wm * 32 + mt * 16 + g;
        int gi0 = row0 + rl, gi1 = gi0 + 8;
        #pragma unroll
        for (int nt = 0; nt < 8; nt++) {
            int cl = wn * 64 + nt * 8 + 2 * t4;
            int gj = col0 + cl;
            int ib = rl - cl + 127;
            float v0 = acc[mt][nt][0] * 0.125f + dwin[ib];
            float v1 = acc[mt][nt][1] * 0.125f + dwin[ib - 1];
            float v2 = acc[mt][nt][2] * 0.125f + dwin[ib + 8];
            float v3 = acc[mt][nt][3] * 0.125f + dwin[ib + 7];
            float p0 = __expf(v0), p1 = __expf(v1);
            float p2 = __expf(v2), p3 = __expf(v3);
            rsum[mt][0] += p0 + p1;
            rsum[mt][1] += p2 + p3;
            *(float2*)&attn[((size_t)bh * S + gi0) * S + gj] = make_float2(p0, p1);
            *(float2*)&attn[((size_t)bh * S + gi1) * S + gj] = make_float2(p2, p3);
        }
    }
    #pragma unroll
    for (int mt = 0; mt < 2; mt++)
        #pragma unroll
        for (int h2 = 0; h2 < 2; h2++) {
            float v = rsum[mt][h2];
            v += __shfl_xor_sync(0xffffffffu, v, 1);
            v += __shfl_xor_sync(0xffffffffu, v, 2);
            if (t4 == 0) atomicAdd(&ssum[wm * 32 + mt * 16 + h2 * 8 + g], v);
        }
    __syncthreads();
    if (tid < 128) atomicAdd(&g_rowsum[(size_t)bh * S + row0 + tid], ssum[tid]);
}

// ---------------- attn@V: pipelined (register prefetch) + in-place normalize (R9 winner) ----------------
__global__ __launch_bounds__(256, 2) void attnv_kernel(float* __restrict__ attn)
{
    extern __shared__ __align__(16) float sm[];
    float* Phi = sm;
    float* Plo = sm + 128 * 68;
    float* Vt  = sm + 2 * 128 * 68;

    const int bh = blockIdx.y, row0 = blockIdx.x * 128;
    const int bb = bh >> 3, hh = bh & 7;
    const int tid = threadIdx.x, lane = tid & 31, wid = tid >> 5;
    const int g = lane >> 2, t4 = lane & 3, wm = wid >> 1, wn = wid & 1;

    const int r_p = tid >> 4;
    const int c4 = (tid & 15) * 4;

    float* gp0 = attn + ((size_t)bh * S + row0 + r_p) * S + c4;
    const float* vp0 = g_v + ((size_t)bh * S + r_p) * DK + c4;

    float invr[8];
    #pragma unroll
    for (int i = 0; i < 8; i++)
        invr[i] = 1.0f / g_rowsum[(size_t)bh * S + row0 + i * 16 + r_p];

    float acc[2][4][4] = {};

    float4 pv[8], vv[4];
    #pragma unroll
    for (int i = 0; i < 8; i++) pv[i] = *(const float4*)(gp0 + (size_t)i * 16 * S);
    #pragma unroll
    for (int i = 0; i < 4; i++) vv[i] = *(const float4*)(vp0 + i * 16 * DK);

    for (int kt = 0; kt < 32; kt++) {
        #pragma unroll
        for (int i = 0; i < 8; i++) {
            int r = i * 16 + r_p;
            float4 a = pv[i];
            float inv = invr[i];
            a.x *= inv; a.y *= inv; a.z *= inv; a.w *= inv;
            *(float4*)(gp0 + (size_t)i * 16 * S) = a;
            unsigned h0, l0, h1, l1, h2, l2, h3, l3;
            split_tf32(a.x, h0, l0); split_tf32(a.y, h1, l1);
            split_tf32(a.z, h2, l2); split_tf32(a.w, h3, l3);
            *(float4*)&Phi[r * 68 + c4] = make_float4(
                __uint_as_float(h0), __uint_as_float(h1),
                __uint_as_float(h2), __uint_as_float(h3));
            *(float4*)&Plo[r * 68 + c4] = make_float4(
                __uint_as_float(l0), __uint_as_float(l1),
                __uint_as_float(l2), __uint_as_float(l3));
        }
        #pragma unroll
        for (int i = 0; i < 4; i++) {
            int r = i * 16 + r_p;
            *(float4*)&Vt[r * 72 + c4] = make_float4(
                __uint_as_float(cvt_tf32(vv[i].x)), __uint_as_float(cvt_tf32(vv[i].y)),
                __uint_as_float(cvt_tf32(vv[i].z)), __uint_as_float(cvt_tf32(vv[i].w)));
        }
        gp0 += 64;
        __syncthreads();

        if (kt + 1 < 32) {
            #pragma unroll
            for (int i = 0; i < 8; i++)
                pv[i] = *(const float4*)(gp0 + (size_t)i * 16 * S);
            const float* vp = vp0 + (size_t)(kt + 1) * 64 * DK;
            #pragma unroll
            for (int i = 0; i < 4; i++)
                vv[i] = *(const float4*)(vp + i * 16 * DK);
        }

        #pragma unroll
        for (int ks = 0; ks < 8; ks++) {
            const int kk = ks * 8;
            unsigned ahi[2][4], alo[2][4], bb2[4][2];
            #pragma unroll
            for (int mt = 0; mt < 2; mt++) {
                int base = (wm * 32 + mt * 16 + g) * 68 + kk;
                ahi[mt][0] = __float_as_uint(Phi[base + t4]);
                ahi[mt][1] = __float_as_uint(Phi[base + 8 * 68 + t4]);
                ahi[mt][2] = __float_as_uint(Phi[base + t4 + 4]);
                ahi[mt][3] = __float_as_uint(Phi[base + 8 * 68 + t4 + 4]);
                alo[mt][0] = __float_as_uint(Plo[base + t4]);
                alo[mt][1] = __float_as_uint(Plo[base + 8 * 68 + t4]);
                alo[mt][2] = __float_as_uint(Plo[base + t4 + 4]);
                alo[mt][3] = __float_as_uint(Plo[base + 8 * 68 + t4 + 4]);
            }
            #pragma unroll
            for (int nt = 0; nt < 4; nt++) {
                int n = wn * 32 + nt * 8 + g;
                bb2[nt][0] = __float_as_uint(Vt[(kk + t4) * 72 + n]);
                bb2[nt][1] = __float_as_uint(Vt[(kk + t4 + 4) * 72 + n]);
            }
            #pragma unroll
            for (int mt = 0; mt < 2; mt++)
                #pragma unroll
                for (int nt = 0; nt < 4; nt++)
                    mma8(acc[mt][nt], ahi[mt], bb2[nt]);
            #pragma unroll
            for (int mt = 0; mt < 2; mt++)
                #pragma unroll
                for (int nt = 0; nt < 4; nt++)
                    mma8(acc[mt][nt], alo[mt], bb2[nt]);
        }
        __syncthreads();
    }

    #pragma unroll
    for (int mt = 0; mt < 2; mt++) {
        int rl = wm * 32 + mt * 16 + g;
        size_t tok0 = (size_t)bb * S + row0 + rl;
        size_t tok1 = tok0 + 8;
        #pragma unroll
        for (int nt = 0; nt < 4; nt++) {
            int dk = wn * 32 + nt * 8 + 2 * t4;
            *(float2*)&g_o[tok0 * D + hh * 64 + dk] =
                make_float2(acc[mt][nt][0], acc[mt][nt][1]);
            *(float2*)&g_o[tok1 * D + hh * 64 + dk] =
                make_float2(acc[mt][nt][2], acc[mt][nt][3]);
        }
    }
}

// ---------------- gate scalar ----------------
__global__ void gate_kernel(const float* __restrict__ g2w,
                            const float* __restrict__ g2b)
{
    int warp = (blockIdx.x * blockDim.x + threadIdx.x) >> 5;
    int lane = threadIdx.x & 31;
    if (warp >= NB) return;
    float sum = 0.0f;
    #pragma unroll
    for (int i = 0; i < DH / 32; i++)
        sum += g_hidden[warp * DH + i * 32 + lane] * g2w[i * 32 + lane];
    #pragma unroll
    for (int off = 16; off; off >>= 1)
        sum += __shfl_down_sync(0xffffffffu, sum, off);
    if (lane == 0)
        g_gate[warp] = 1.0f / (1.0f + expf(-(sum + g2b[0])));
}

// ---------------- gated residual + LayerNorm ----------------
__global__ __launch_bounds__(256) void ln_kernel(
    const float* __restrict__ x,
    const float* __restrict__ lng, const float* __restrict__ lnb,
    float* __restrict__ y)
{
    __shared__ float s1[8], s2[8];
    const int n = blockIdx.x;
    const int tid = threadIdx.x;
    const float g = g_gate[n];

    int j0 = tid * 2;
    float2 pr = *(const float2*)&g_proj[n * D + j0];
    float2 xr = *(const float2*)&x[n * D + j0];
    float o0 = pr.x * g + xr.x * (1.0f - g);
    float o1 = pr.y * g + xr.y * (1.0f - g);

    float sum = o0 + o1, sq = o0 * o0 + o1 * o1;
    #pragma unroll
    for (int off = 16; off; off >>= 1) {
        sum += __shfl_down_sync(0xffffffffu, sum, off);
        sq  += __shfl_down_sync(0xffffffffu, sq,  off);
    }
    int wid = tid >> 5, lane = tid & 31;
    if (lane == 0) { s1[wid] = sum; s2[wid] = sq; }
    __syncthreads();
    if (tid == 0) {
        float a = 0.0f, b2 = 0.0f;
        #pragma unroll
        for (int w = 0; w < 8; w++) { a += s1[w]; b2 += s2[w]; }
        s1[0] = a; s2[0] = b2;
    }
    __syncthreads();
    float mean = s1[0] * (1.0f / D);
    float var  = s2[0] * (1.0f / D) - mean * mean;
    float invs = rsqrtf(var + LN_EPS);
    y[n * D + j0]     = (o0 - mean) * invs * lng[j0]     + lnb[j0];
    y[n * D + j0 + 1] = (o1 - mean) * invs * lng[j0 + 1] + lnb[j0 + 1];
}

// ---------------- launch ----------------
extern "C" void kernel_launch(void* const* d_in, const int* in_sizes, int n_in,
                              void* d_out, int out_size)
{
    (void)in_sizes; (void)n_in; (void)out_size;
    const float* x   = (const float*)d_in[0];
    const float* wq  = (const float*)d_in[1];
    const float* bq  = (const float*)d_in[2];
    const float* wk  = (const float*)d_in[3];
    const float* bk  = (const float*)d_in[4];
    const float* wv  = (const float*)d_in[5];
    const float* bv  = (const float*)d_in[6];
    const float* wo  = (const float*)d_in[7];
    const float* bo  = (const float*)d_in[8];
    const float* g1w = (const float*)d_in[9];
    const float* g1b = (const float*)d_in[10];
    const float* g2w = (const float*)d_in[11];
    const float* g2b = (const float*)d_in[12];
    const float* lng = (const float*)d_in[13];
    const float* lnb = (const float*)d_in[14];

    float* y    = (float*)d_out;
    float* attn = y + (size_t)NB * D;

    const int SMEM_SC = (2 * 128 * 68 + 128 + 256) * (int)sizeof(float);      // 71168
    const int SMEM_AV = (2 * 128 * 68 + 64 * 72) * (int)sizeof(float);        // 88064
    cudaFuncSetAttribute(scores_kernel,
                         cudaFuncAttributeMaxDynamicSharedMemorySize, SMEM_SC);
    cudaFuncSetAttribute(attnv_kernel,
                         cudaFuncAttributeMaxDynamicSharedMemorySize, SMEM_AV);

    init_kernel<<<(BH * S + 255) / 256, 256>>>();
    qkv_mma_kernel<<<dim3(4, 32, 3), 256>>>(x, wq, bq, wk, bk, wv, bv);
    scores_kernel<<<dim3(16, 16, 16), 256, SMEM_SC>>>(attn);
    attnv_kernel<<<dim3(16, 16), 256, SMEM_AV>>>(attn);
    proj_mma_kernel<1><<<dim3(4, 32), 256>>>(nullptr, wo, bo, 512);
    proj_mma_kernel<2><<<dim3(2, 32), 256>>>(x, g1w, g1b, 256);
    gate_kernel<<<(NB * 32) / 256, 256>>>(g2w, g2b);
    ln_kernel<<<NB, 256>>>(x, lng, lnb, y);
}